// round 1
// baseline (speedup 1.0000x reference)
#include <cuda_runtime.h>
#include <math.h>

#define Bsz 32
#define Pn  196
#define Dn  2048
#define Hn  512
#define Vn  30000
#define Tn  19

// ---------------- scratch (device globals; no allocations allowed) ----------
__device__ float g_avg[Bsz * Dn];
__device__ float g_h[Bsz * Hn];
__device__ float g_c[Bsz * Hn];
__device__ float g_att_img[Bsz * Pn * Hn];     // 12.85 MB
__device__ float g_emb[Bsz * Tn * Hn];
__device__ float g_hproj[Bsz * Hn];
__device__ float g_e[Bsz * Pn];
__device__ float g_alpha[Bsz * Pn];
__device__ float g_context[Bsz * Dn];
__device__ float g_gate[Bsz * Dn];
__device__ float g_x[Bsz * (Hn + Dn)];
__device__ float g_gates[Bsz * 4 * Hn];

__device__ __forceinline__ float sigf(float x) { return 1.f / (1.f + expf(-x)); }

// ---------------- generic register-tiled GEMM: C[M,N] = act(A[M,K]@B[K,N] + b1 + b2 [+C]) ---
// BM=32 fixed, BK=16. A row-major lda=K, B row-major ldb=N, C row stride = ldc.
// act: 0 none, 1 tanh, 2 sigmoid. accum: add pre-existing C.
template <int BN, int TM, int TN>
__global__ void gemm_kernel(const float* __restrict__ A, const float* __restrict__ B,
                            const float* __restrict__ bias1, const float* __restrict__ bias2,
                            float* __restrict__ C, int N, int K, int ldc,
                            int act, int accum)
{
    constexpr int BM = 32, BK = 16;
    constexpr int NT = (BM / TM) * (BN / TN);
    __shared__ float As[BK][BM + 4];   // pad to 36 floats: 16B-aligned rows, low conflicts
    __shared__ float Bs[BK][BN];

    const int tid  = threadIdx.x;
    const int tx   = tid % (BN / TN);
    const int ty   = tid / (BN / TN);
    const int row0 = blockIdx.y * BM;
    const int n0   = blockIdx.x * BN;

    float acc[TM][TN];
#pragma unroll
    for (int i = 0; i < TM; i++)
#pragma unroll
        for (int j = 0; j < TN; j++) acc[i][j] = 0.f;

    for (int k0 = 0; k0 < K; k0 += BK) {
#pragma unroll
        for (int i = tid; i < BM * BK; i += NT) {
            int m = i >> 4, k = i & 15;
            As[k][m] = A[(size_t)(row0 + m) * K + k0 + k];
        }
#pragma unroll
        for (int i = tid; i < BK * BN; i += NT) {
            int k = i / BN, n = i % BN;
            int gn = n0 + n;
            Bs[k][n] = (gn < N) ? B[(size_t)(k0 + k) * N + gn] : 0.f;
        }
        __syncthreads();
#pragma unroll
        for (int kk = 0; kk < BK; kk++) {
            float a[TM], bb[TN];
#pragma unroll
            for (int i = 0; i < TM; i++) a[i] = As[kk][ty * TM + i];
#pragma unroll
            for (int j = 0; j < TN; j++) bb[j] = Bs[kk][tx * TN + j];
#pragma unroll
            for (int i = 0; i < TM; i++)
#pragma unroll
                for (int j = 0; j < TN; j++)
                    acc[i][j] = fmaf(a[i], bb[j], acc[i][j]);
        }
        __syncthreads();
    }

#pragma unroll
    for (int i = 0; i < TM; i++) {
        int r = row0 + ty * TM + i;
#pragma unroll
        for (int j = 0; j < TN; j++) {
            int gn = n0 + tx * TN + j;
            if (gn < N) {
                float v = acc[i][j];
                if (bias1) v += bias1[gn];
                if (bias2) v += bias2[gn];
                float* cp = C + (size_t)r * ldc + gn;
                if (accum) v += *cp;
                if (act == 1) v = tanhf(v);
                else if (act == 2) v = sigf(v);
                *cp = v;
            }
        }
    }
}

// ---------------- mean-pool over P: g_avg[b,d] ----------------
__global__ void avg_kernel(const float* __restrict__ img)
{
    int idx = blockIdx.x * blockDim.x + threadIdx.x;   // float4 index over [B, D/4]
    if (idx >= Bsz * (Dn / 4)) return;
    int b = idx >> 9;              // Dn/4 = 512
    int d4 = idx & 511;
    const float4* ip = (const float4*)img + (size_t)b * Pn * (Dn / 4) + d4;
    float4 s = make_float4(0.f, 0.f, 0.f, 0.f);
    for (int p = 0; p < Pn; p++) {
        float4 x = ip[(size_t)p * (Dn / 4)];
        s.x += x.x; s.y += x.y; s.z += x.z; s.w += x.w;
    }
    s.x /= (float)Pn; s.y /= (float)Pn; s.z /= (float)Pn; s.w /= (float)Pn;
    ((float4*)g_avg)[idx] = s;
}

// ---------------- embedding gather: g_emb[b,t,h] = E[captions[b,t], h], t<T ---
__global__ void emb_kernel(const int* __restrict__ caps, const float* __restrict__ E)
{
    int idx = blockIdx.x * blockDim.x + threadIdx.x;
    if (idx >= Bsz * Tn * Hn) return;
    int b = idx / (Tn * Hn);
    int r = idx - b * Tn * Hn;
    int t = r / Hn;
    int h = r - t * Hn;
    int tok = caps[b * 20 + t];
    g_emb[idx] = E[(size_t)tok * Hn + h];
}

// ---------------- attention scores: e[b,p] = sum_h tanh(att_img+hproj)*v + bv ---
__global__ void scores_kernel(const float* __restrict__ v_att, const float* __restrict__ b_v_att)
{
    int w = (blockIdx.x * blockDim.x + threadIdx.x) >> 5;  // warp per (b,p)
    int lane = threadIdx.x & 31;
    if (w >= Bsz * Pn) return;
    int b = w / Pn;
    const float* ai = g_att_img + (size_t)w * Hn;
    const float* hp = g_hproj + b * Hn;
    float s = 0.f;
#pragma unroll
    for (int i = 0; i < Hn / 32; i++) {
        int h = lane + 32 * i;
        s += tanhf(ai[h] + hp[h]) * v_att[h];
    }
#pragma unroll
    for (int o = 16; o; o >>= 1) s += __shfl_down_sync(0xffffffffu, s, o);
    if (lane == 0) g_e[w] = s + b_v_att[0];
}

// ---------------- softmax over P per batch; also writes alphas output ----------
__global__ void softmax_kernel(float* __restrict__ out_alphas, int t)
{
    int b = blockIdx.x;
    int tid = threadIdx.x;                 // 256 threads
    __shared__ float sred[32];
    float v = (tid < Pn) ? g_e[b * Pn + tid] : -1e30f;

    float m = v;
#pragma unroll
    for (int o = 16; o; o >>= 1) m = fmaxf(m, __shfl_xor_sync(0xffffffffu, m, o));
    if ((tid & 31) == 0) sred[tid >> 5] = m;
    __syncthreads();
    if (tid < 32) {
        float mm = (tid < 8) ? sred[tid] : -1e30f;
#pragma unroll
        for (int o = 4; o; o >>= 1) mm = fmaxf(mm, __shfl_xor_sync(0xffffffffu, mm, o));
        if (tid == 0) sred[0] = mm;
    }
    __syncthreads();
    float bm = sred[0];
    float ex = (tid < Pn) ? expf(v - bm) : 0.f;
    __syncthreads();

    float s = ex;
#pragma unroll
    for (int o = 16; o; o >>= 1) s += __shfl_xor_sync(0xffffffffu, s, o);
    if ((tid & 31) == 0) sred[tid >> 5] = s;
    __syncthreads();
    if (tid < 32) {
        float ss = (tid < 8) ? sred[tid] : 0.f;
#pragma unroll
        for (int o = 4; o; o >>= 1) ss += __shfl_xor_sync(0xffffffffu, ss, o);
        if (tid == 0) sred[0] = ss;
    }
    __syncthreads();
    if (tid < Pn) {
        float a = ex / sred[0];
        g_alpha[b * Pn + tid] = a;
        out_alphas[((size_t)b * Tn + t) * Pn + tid] = a;
    }
}

// ---------------- context[b,d] = sum_p alpha[b,p] * img[b,p,d] -----------------
__global__ void context_kernel(const float* __restrict__ img)
{
    int b = blockIdx.x >> 1;               // 2 blocks per batch row
    int chunk = blockIdx.x & 1;
    int tid = threadIdx.x;                 // 256
    __shared__ float sal[Pn];
    if (tid < Pn) sal[tid] = g_alpha[b * Pn + tid];
    __syncthreads();
    int d4 = chunk * 256 + tid;            // float4 index, Dn/4 = 512 per b
    const float4* ip = (const float4*)img + (size_t)b * Pn * (Dn / 4) + d4;
    float4 s = make_float4(0.f, 0.f, 0.f, 0.f);
    for (int p = 0; p < Pn; p++) {
        float a = sal[p];
        float4 x = ip[(size_t)p * (Dn / 4)];
        s.x = fmaf(a, x.x, s.x); s.y = fmaf(a, x.y, s.y);
        s.z = fmaf(a, x.z, s.z); s.w = fmaf(a, x.w, s.w);
    }
    ((float4*)g_context)[b * (Dn / 4) + d4] = s;
}

// ---------------- build LSTM input x = [emb_t, gate*context] -------------------
__global__ void build_x_kernel(int t)
{
    int idx = blockIdx.x * blockDim.x + threadIdx.x;
    if (idx >= Bsz * (Hn + Dn)) return;
    int b = idx / (Hn + Dn);
    int j = idx - b * (Hn + Dn);
    if (j < Hn) {
        g_x[idx] = g_emb[((size_t)b * Tn + t) * Hn + j];
    } else {
        int d = j - Hn;
        g_x[idx] = g_gate[b * Dn + d] * g_context[b * Dn + d];
    }
}

// ---------------- LSTM pointwise update ----------------------------------------
__global__ void lstm_kernel()
{
    int idx = blockIdx.x * blockDim.x + threadIdx.x;
    if (idx >= Bsz * Hn) return;
    int b = idx / Hn;
    int j = idx - b * Hn;
    const float* gr = g_gates + b * 4 * Hn;
    float i_ = gr[j];
    float f_ = gr[Hn + j];
    float gg = gr[2 * Hn + j];
    float o_ = gr[3 * Hn + j];
    float c = sigf(f_) * g_c[idx] + sigf(i_) * tanhf(gg);
    g_c[idx] = c;
    g_h[idx] = sigf(o_) * tanhf(c);
}

// ================================================================================
extern "C" void kernel_launch(void* const* d_in, const int* in_sizes, int n_in,
                              void* d_out, int out_size)
{
    const float* img      = (const float*)d_in[0];
    const int*   caps     = (const int*)d_in[1];
    const float* Wih      = (const float*)d_in[2];
    const float* Whh      = (const float*)d_in[3];
    const float* bih      = (const float*)d_in[4];
    const float* bhh      = (const float*)d_in[5];
    const float* W_init_h = (const float*)d_in[6];
    const float* b_init_h = (const float*)d_in[7];
    const float* W_init_c = (const float*)d_in[8];
    const float* b_init_c = (const float*)d_in[9];
    const float* W_fbeta  = (const float*)d_in[10];
    const float* b_fbeta  = (const float*)d_in[11];
    const float* W_out    = (const float*)d_in[12];
    const float* b_out    = (const float*)d_in[13];
    const float* W_att_im = (const float*)d_in[14];
    const float* b_att_im = (const float*)d_in[15];
    const float* W_att_h  = (const float*)d_in[16];
    const float* b_att_h  = (const float*)d_in[17];
    const float* v_att    = (const float*)d_in[18];
    const float* b_v_att  = (const float*)d_in[19];
    const float* E        = (const float*)d_in[20];

    float* preds  = (float*)d_out;                              // [B,T,V]
    float* alphas = (float*)d_out + (size_t)Bsz * Tn * Vn;      // [B,T,P]

    float *p_avg, *p_h, *p_c, *p_att, *p_hproj, *p_gate, *p_x, *p_gates;
    cudaGetSymbolAddress((void**)&p_avg,   g_avg);
    cudaGetSymbolAddress((void**)&p_h,     g_h);
    cudaGetSymbolAddress((void**)&p_c,     g_c);
    cudaGetSymbolAddress((void**)&p_att,   g_att_img);
    cudaGetSymbolAddress((void**)&p_hproj, g_hproj);
    cudaGetSymbolAddress((void**)&p_gate,  g_gate);
    cudaGetSymbolAddress((void**)&p_x,     g_x);
    cudaGetSymbolAddress((void**)&p_gates, g_gates);

    // ---- setup ----
    avg_kernel<<<64, 256>>>(img);
    // h0 = tanh(avg @ W_init_h + b), c0 = tanh(avg @ W_init_c + b)
    gemm_kernel<32, 4, 1><<<dim3(16, 1), 256>>>(p_avg, W_init_h, b_init_h, nullptr,
                                                p_h, Hn, Dn, Hn, 1, 0);
    gemm_kernel<32, 4, 1><<<dim3(16, 1), 256>>>(p_avg, W_init_c, b_init_c, nullptr,
                                                p_c, Hn, Dn, Hn, 1, 0);
    // att_img = img @ W_att_img + b   (M = B*P = 6272)
    gemm_kernel<128, 4, 4><<<dim3(4, (Bsz * Pn) / 32), 256>>>(img, W_att_im, b_att_im, nullptr,
                                                              p_att, Hn, Dn, Hn, 0, 0);
    emb_kernel<<<(Bsz * Tn * Hn) / 256, 256>>>(caps, E);

    // ---- recurrent steps ----
    for (int t = 0; t < Tn; t++) {
        // hproj = h @ W_att_h + b_att_h
        gemm_kernel<32, 4, 1><<<dim3(16, 1), 256>>>(p_h, W_att_h, b_att_h, nullptr,
                                                    p_hproj, Hn, Hn, Hn, 0, 0);
        scores_kernel<<<(Bsz * Pn) / 8, 256>>>(v_att, b_v_att);
        softmax_kernel<<<Bsz, 256>>>(alphas, t);
        context_kernel<<<Bsz * 2, 256>>>(img);
        // gate = sigmoid(h @ W_fbeta + b_fbeta)
        gemm_kernel<32, 4, 1><<<dim3(64, 1), 256>>>(p_h, W_fbeta, b_fbeta, nullptr,
                                                    p_gate, Dn, Hn, Dn, 2, 0);
        build_x_kernel<<<(Bsz * (Hn + Dn)) / 256, 256>>>(t);
        // gates = x @ Wih + (bih + bhh); then += h @ Whh
        gemm_kernel<32, 4, 1><<<dim3(64, 1), 256>>>(p_x, Wih, bih, bhh,
                                                    p_gates, 4 * Hn, Hn + Dn, 4 * Hn, 0, 0);
        gemm_kernel<32, 4, 1><<<dim3(64, 1), 256>>>(p_h, Whh, nullptr, nullptr,
                                                    p_gates, 4 * Hn, Hn, 4 * Hn, 0, 1);
        lstm_kernel<<<(Bsz * Hn) / 256, 256>>>();
        // preds[:, t, :] = h @ W_out + b_out
        gemm_kernel<128, 4, 4><<<dim3((Vn + 127) / 128, 1), 256>>>(p_h, W_out, b_out, nullptr,
                                                                   preds + (size_t)t * Vn,
                                                                   Vn, Hn, (size_t)Tn * Vn, 0, 0);
    }
}

// round 2
// speedup vs baseline: 5.9849x; 5.9849x over previous
#include <cuda_runtime.h>
#include <math.h>

#define Bsz 32
#define Pn  196
#define Dn  2048
#define Hn  512
#define Vn  30000
#define Tn  19

// ---------------- scratch (device globals) ----------------
__device__ float g_avg[Bsz * Dn];
__device__ float g_h[Bsz * Hn];
__device__ float g_c[Bsz * Hn];
__device__ float g_hall[Tn * Bsz * Hn];          // h after each step, rows = t*32+b
__device__ float g_att_img[Bsz * Pn * Hn];       // 12.85 MB
__device__ float g_emb[Bsz * Tn * Hn];           // rows = b*19+t
__device__ float g_embW[Bsz * Tn * 4 * Hn];      // emb @ Wih_top, rows = b*19+t
__device__ float g_hproj[Bsz * Hn];
__device__ float g_gate[Bsz * Dn];
__device__ float g_xc[Bsz * Dn];                 // gate * context
__device__ float g_e[Bsz * Pn];
__device__ float g_alpha[Bsz * Pn];
// split-K partial buffers
__device__ float g_pp_h[2 * Bsz * Hn];           // hproj partials (ks=2)
__device__ float g_pp_g[2 * Bsz * Dn];           // gate partials (ks=2)
__device__ float g_pa[4 * Bsz * 4 * Hn];         // xc@Wih_bot partials (ks=4)
__device__ float g_pb[1 * Bsz * 4 * Hn];         // h@Whh
__device__ float g_pi_h[8 * Bsz * Hn];           // init h partials (ks=8)
__device__ float g_pi_c[8 * Bsz * Hn];

__device__ __forceinline__ float sigf(float x) { return 1.f / (1.f + expf(-x)); }

// ============ big GEMM: C[M,N] = A[M,K]@B[K,N] + bias ============
// BM=64, BN=64, BK=32, TM=8, TN=4, 128 threads. OUTMAP=1 -> preds layout remap.
template <int OUTMAP>
__global__ __launch_bounds__(128)
void gemm_big(const float* __restrict__ A, int lda,
              const float* __restrict__ B, int ldb,
              const float* __restrict__ bias,
              float* __restrict__ C, int ldc,
              int M, int N, int K)
{
    constexpr int BM = 64, BN = 64, BK = 32;
    __shared__ float As[BM][BK + 4];
    __shared__ float Bs[BK][BN];

    const int tid = threadIdx.x;
    const int tx = tid & 15;          // 0..15 -> n
    const int ty = tid >> 4;          // 0..7  -> m
    const int row0 = blockIdx.y * BM;
    const int n0   = blockIdx.x * BN;

    const int arow = tid >> 3;        // 0..15
    const int ac4  = tid & 7;         // col4 0..7
    const int brow = tid >> 4;        // 0..7
    const int bc4  = tid & 15;        // col4 0..15

    float acc[8][4];
#pragma unroll
    for (int i = 0; i < 8; i++)
#pragma unroll
        for (int j = 0; j < 4; j++) acc[i][j] = 0.f;

    const float4 z4 = make_float4(0.f, 0.f, 0.f, 0.f);

    for (int k0 = 0; k0 < K; k0 += BK) {
#pragma unroll
        for (int i = 0; i < 4; i++) {
            int r = row0 + arow + 16 * i;
            float4 v = (r < M) ? *(const float4*)(A + (size_t)r * lda + k0 + ac4 * 4) : z4;
            *(float4*)&As[arow + 16 * i][ac4 * 4] = v;
        }
        int gn = n0 + bc4 * 4;
#pragma unroll
        for (int i = 0; i < 4; i++) {
            int kk = brow + 8 * i;
            float4 v = (gn < N) ? *(const float4*)(B + (size_t)(k0 + kk) * ldb + gn) : z4;
            *(float4*)&Bs[kk][bc4 * 4] = v;
        }
        __syncthreads();
#pragma unroll
        for (int kk = 0; kk < BK; kk++) {
            float a[8];
#pragma unroll
            for (int i = 0; i < 8; i++) a[i] = As[ty * 8 + i][kk];
            float4 bv = *(float4*)&Bs[kk][tx * 4];
#pragma unroll
            for (int i = 0; i < 8; i++) {
                acc[i][0] = fmaf(a[i], bv.x, acc[i][0]);
                acc[i][1] = fmaf(a[i], bv.y, acc[i][1]);
                acc[i][2] = fmaf(a[i], bv.z, acc[i][2]);
                acc[i][3] = fmaf(a[i], bv.w, acc[i][3]);
            }
        }
        __syncthreads();
    }

#pragma unroll
    for (int i = 0; i < 8; i++) {
        int r = row0 + ty * 8 + i;
        if (r >= M) continue;
#pragma unroll
        for (int j = 0; j < 4; j++) {
            int gn = n0 + tx * 4 + j;
            if (gn >= N) continue;
            float v = acc[i][j];
            if (bias) v += bias[gn];
            if (OUTMAP) {
                int b = r & 31, t = r >> 5;            // rows = t*32+b
                C[((size_t)b * Tn + t) * Vn + gn] = v;
            } else {
                C[(size_t)r * ldc + gn] = v;
            }
        }
    }
}

// ============ small GEMM pass: two segments, split-K partials ============
// M=32 fixed. BM=32, BN=32, BK=32, TM=4, TN=4, 64 threads.
// Partial out: P + ksi*32*N + m*N + n
__global__ __launch_bounds__(64)
void gemm_pass(const float* A0, int lda0, const float* B0, int ldb0, float* P0, int N0, int K0, int ks0, int nt0,
               const float* A1, int lda1, const float* B1, int ldb1, float* P1, int N1, int K1, int ks1, int nt1)
{
    const float* A; const float* B; float* P;
    int N, K, ks, nt, lda, ldb;
    int id = blockIdx.x;
    int blocks0 = nt0 * ks0;
    if (id < blocks0) { A=A0; B=B0; P=P0; N=N0; K=K0; ks=ks0; nt=nt0; lda=lda0; ldb=ldb0; }
    else { id -= blocks0; A=A1; B=B1; P=P1; N=N1; K=K1; ks=ks1; nt=nt1; lda=lda1; ldb=ldb1; }

    int ntile = id % nt;
    int ksi   = id / nt;
    int kLen  = K / ks;
    int kbeg  = ksi * kLen;
    int kend  = kbeg + kLen;
    int n0    = ntile * 32;

    __shared__ float As[32][36];
    __shared__ float Bs[32][32];

    const int tid = threadIdx.x;
    const int tx = tid & 7;     // 0..7 -> n
    const int ty = tid >> 3;    // 0..7 -> m
    const int lrow = tid >> 3;  // 0..7
    const int lc4  = tid & 7;   // 0..7

    float acc[4][4];
#pragma unroll
    for (int i = 0; i < 4; i++)
#pragma unroll
        for (int j = 0; j < 4; j++) acc[i][j] = 0.f;

    for (int k0 = kbeg; k0 < kend; k0 += 32) {
#pragma unroll
        for (int i = 0; i < 4; i++)
            *(float4*)&As[lrow + 8 * i][lc4 * 4] =
                *(const float4*)(A + (size_t)(lrow + 8 * i) * lda + k0 + lc4 * 4);
#pragma unroll
        for (int i = 0; i < 4; i++)
            *(float4*)&Bs[lrow + 8 * i][lc4 * 4] =
                *(const float4*)(B + (size_t)(k0 + lrow + 8 * i) * ldb + n0 + lc4 * 4);
        __syncthreads();
#pragma unroll
        for (int kk = 0; kk < 32; kk++) {
            float a[4];
#pragma unroll
            for (int i = 0; i < 4; i++) a[i] = As[ty * 4 + i][kk];
            float4 bv = *(float4*)&Bs[kk][tx * 4];
#pragma unroll
            for (int i = 0; i < 4; i++) {
                acc[i][0] = fmaf(a[i], bv.x, acc[i][0]);
                acc[i][1] = fmaf(a[i], bv.y, acc[i][1]);
                acc[i][2] = fmaf(a[i], bv.z, acc[i][2]);
                acc[i][3] = fmaf(a[i], bv.w, acc[i][3]);
            }
        }
        __syncthreads();
    }

    float* dst = P + (size_t)ksi * 32 * N;
#pragma unroll
    for (int i = 0; i < 4; i++) {
        int m = ty * 4 + i;
#pragma unroll
        for (int j = 0; j < 4; j++)
            dst[(size_t)m * N + n0 + tx * 4 + j] = acc[i][j];
    }
}

// ============ reduce two split-K partial sets, with bias + activation ============
// act: 0 none, 1 tanh, 2 sigmoid. cnt0 must be a multiple of 256.
__global__ void reduce2_kernel(float* d0, const float* P0, int ks0, int N0, const float* b0, int act0, int cnt0,
                               float* d1, const float* P1, int ks1, int N1, const float* b1, int act1, int cnt1)
{
    int i = blockIdx.x * 256 + threadIdx.x;
    float* d; const float* P; int ks, N; const float* bi; int act; int cnt;
    if (i < cnt0) { d=d0; P=P0; ks=ks0; N=N0; bi=b0; act=act0; cnt=cnt0; }
    else { i -= cnt0; d=d1; P=P1; ks=ks1; N=N1; bi=b1; act=act1; cnt=cnt1; }
    if (i >= cnt) return;
    float v = 0.f;
    for (int s = 0; s < ks; s++) v += P[(size_t)s * cnt + i];
    if (bi) v += bi[i % N];
    if (act == 1) v = tanhf(v);
    else if (act == 2) v = sigf(v);
    d[i] = v;
}

// ---------------- mean pool ----------------
__global__ void avg_kernel(const float* __restrict__ img)
{
    int idx = blockIdx.x * blockDim.x + threadIdx.x;
    if (idx >= Bsz * (Dn / 4)) return;
    int b = idx >> 9;
    const float4* ip = (const float4*)img + (size_t)b * Pn * (Dn / 4) + (idx & 511);
    float4 s = make_float4(0.f, 0.f, 0.f, 0.f);
    for (int p = 0; p < Pn; p++) {
        float4 x = ip[(size_t)p * (Dn / 4)];
        s.x += x.x; s.y += x.y; s.z += x.z; s.w += x.w;
    }
    const float inv = 1.f / (float)Pn;
    s.x *= inv; s.y *= inv; s.z *= inv; s.w *= inv;
    ((float4*)g_avg)[idx] = s;
}

// ---------------- embedding gather: rows = b*19+t ----------------
__global__ void emb_kernel(const int* __restrict__ caps, const float* __restrict__ E)
{
    int idx = blockIdx.x * blockDim.x + threadIdx.x;
    if (idx >= Bsz * Tn * Hn) return;
    int r = idx / Hn;           // b*19+t
    int h = idx - r * Hn;
    int b = r / Tn, t = r - b * Tn;
    int tok = caps[b * 20 + t];
    g_emb[idx] = E[(size_t)tok * Hn + h];
}

// ---------------- attention scores (tanh.approx) ----------------
__global__ void scores_kernel(const float* __restrict__ v_att, const float* __restrict__ b_v_att)
{
    int w = (blockIdx.x * blockDim.x + threadIdx.x) >> 5;
    int lane = threadIdx.x & 31;
    if (w >= Bsz * Pn) return;
    int b = w / Pn;
    const float* ai = g_att_img + (size_t)w * Hn;
    const float* hp = g_hproj + b * Hn;
    float s = 0.f;
#pragma unroll
    for (int i = 0; i < Hn / 32; i++) {
        int h = lane + 32 * i;
        float x = ai[h] + hp[h];
        float th;
        asm("tanh.approx.f32 %0, %1;" : "=f"(th) : "f"(x));
        s = fmaf(th, v_att[h], s);
    }
#pragma unroll
    for (int o = 16; o; o >>= 1) s += __shfl_down_sync(0xffffffffu, s, o);
    if (lane == 0) g_e[w] = s + b_v_att[0];
}

// ---------------- softmax over P; writes alphas output ----------------
__global__ void softmax_kernel(float* __restrict__ out_alphas, int t)
{
    int b = blockIdx.x;
    int tid = threadIdx.x;                 // 256
    __shared__ float sred[32];
    float v = (tid < Pn) ? g_e[b * Pn + tid] : -1e30f;

    float m = v;
#pragma unroll
    for (int o = 16; o; o >>= 1) m = fmaxf(m, __shfl_xor_sync(0xffffffffu, m, o));
    if ((tid & 31) == 0) sred[tid >> 5] = m;
    __syncthreads();
    if (tid < 32) {
        float mm = (tid < 8) ? sred[tid] : -1e30f;
#pragma unroll
        for (int o = 4; o; o >>= 1) mm = fmaxf(mm, __shfl_xor_sync(0xffffffffu, mm, o));
        if (tid == 0) sred[0] = mm;
    }
    __syncthreads();
    float bm = sred[0];
    float ex = (tid < Pn) ? expf(v - bm) : 0.f;
    __syncthreads();

    float s = ex;
#pragma unroll
    for (int o = 16; o; o >>= 1) s += __shfl_xor_sync(0xffffffffu, s, o);
    if ((tid & 31) == 0) sred[tid >> 5] = s;
    __syncthreads();
    if (tid < 32) {
        float ss = (tid < 8) ? sred[tid] : 0.f;
#pragma unroll
        for (int o = 4; o; o >>= 1) ss += __shfl_xor_sync(0xffffffffu, ss, o);
        if (tid == 0) sred[0] = ss;
    }
    __syncthreads();
    if (tid < Pn) {
        float a = ex / sred[0];
        g_alpha[b * Pn + tid] = a;
        out_alphas[((size_t)b * Tn + t) * Pn + tid] = a;
    }
}

// ---------------- context (p-sliced) fused with gate multiply -> g_xc ----------
__global__ __launch_bounds__(128)
void context_kernel(const float* __restrict__ img)
{
    int bx = blockIdx.x;
    int b  = bx >> 4;           // 16 chunks per batch
    int ch = bx & 15;
    int tid = threadIdx.x;      // 128 = 32 d4-lanes x 4 p-slices
    int dl = tid & 31;
    int ps = tid >> 5;
    __shared__ float  sal[Pn];
    __shared__ float4 red[4][32];
    for (int i = tid; i < Pn; i += 128) sal[i] = g_alpha[b * Pn + i];
    __syncthreads();
    int d4 = ch * 32 + dl;      // float4 index within Dn/4=512
    const float4* ip = (const float4*)img + (size_t)b * Pn * (Dn / 4) + d4;
    float4 s = make_float4(0.f, 0.f, 0.f, 0.f);
    for (int p = ps; p < Pn; p += 4) {
        float a = sal[p];
        float4 x = ip[(size_t)p * (Dn / 4)];
        s.x = fmaf(a, x.x, s.x); s.y = fmaf(a, x.y, s.y);
        s.z = fmaf(a, x.z, s.z); s.w = fmaf(a, x.w, s.w);
    }
    red[ps][dl] = s;
    __syncthreads();
    if (tid < 32) {
        float4 r0 = red[0][tid], r1 = red[1][tid], r2 = red[2][tid], r3 = red[3][tid];
        float4 sum = make_float4(r0.x+r1.x+r2.x+r3.x, r0.y+r1.y+r2.y+r3.y,
                                 r0.z+r1.z+r2.z+r3.z, r0.w+r1.w+r2.w+r3.w);
        int d4g = ch * 32 + tid;
        float4 g = ((const float4*)g_gate)[b * (Dn / 4) + d4g];
        sum.x *= g.x; sum.y *= g.y; sum.z *= g.z; sum.w *= g.w;
        ((float4*)g_xc)[b * (Dn / 4) + d4g] = sum;
    }
}

// ---------------- LSTM update: sums gate partials + embW + biases -------------
__global__ void lstm_kernel(const float* __restrict__ bih, const float* __restrict__ bhh, int t)
{
    int idx = blockIdx.x * blockDim.x + threadIdx.x;
    if (idx >= Bsz * Hn) return;
    int b = idx >> 9;
    int j = idx & 511;
    int rowE = (b * Tn + t) * 4 * Hn;
    int rowP = b * 4 * Hn;

    float gv[4];
#pragma unroll
    for (int g = 0; g < 4; g++) {
        int n = g * Hn + j;
        float v = g_embW[rowE + n] + g_pb[rowP + n] + bih[n] + bhh[n];
#pragma unroll
        for (int s = 0; s < 4; s++) v += g_pa[s * Bsz * 4 * Hn + rowP + n];
        gv[g] = v;
    }
    float c = sigf(gv[1]) * g_c[idx] + sigf(gv[0]) * tanhf(gv[2]);
    g_c[idx] = c;
    float h = sigf(gv[3]) * tanhf(c);
    g_h[idx] = h;
    g_hall[((size_t)t * Bsz + b) * Hn + j] = h;   // rows = t*32+b
}

// ================================================================================
extern "C" void kernel_launch(void* const* d_in, const int* in_sizes, int n_in,
                              void* d_out, int out_size)
{
    const float* img      = (const float*)d_in[0];
    const int*   caps     = (const int*)d_in[1];
    const float* Wih      = (const float*)d_in[2];
    const float* Whh      = (const float*)d_in[3];
    const float* bih      = (const float*)d_in[4];
    const float* bhh      = (const float*)d_in[5];
    const float* W_init_h = (const float*)d_in[6];
    const float* b_init_h = (const float*)d_in[7];
    const float* W_init_c = (const float*)d_in[8];
    const float* b_init_c = (const float*)d_in[9];
    const float* W_fbeta  = (const float*)d_in[10];
    const float* b_fbeta  = (const float*)d_in[11];
    const float* W_out    = (const float*)d_in[12];
    const float* b_out    = (const float*)d_in[13];
    const float* W_att_im = (const float*)d_in[14];
    const float* b_att_im = (const float*)d_in[15];
    const float* W_att_h  = (const float*)d_in[16];
    const float* b_att_h  = (const float*)d_in[17];
    const float* v_att    = (const float*)d_in[18];
    const float* b_v_att  = (const float*)d_in[19];
    const float* E        = (const float*)d_in[20];

    float* preds  = (float*)d_out;                              // [B,T,V]
    float* alphas = (float*)d_out + (size_t)Bsz * Tn * Vn;      // [B,T,P]

    float *p_avg, *p_h, *p_c, *p_att, *p_hproj, *p_gate, *p_xc, *p_emb, *p_embW, *p_hall;
    float *p_pph, *p_ppg, *p_pa, *p_pb, *p_pih, *p_pic;
    cudaGetSymbolAddress((void**)&p_avg,   g_avg);
    cudaGetSymbolAddress((void**)&p_h,     g_h);
    cudaGetSymbolAddress((void**)&p_c,     g_c);
    cudaGetSymbolAddress((void**)&p_att,   g_att_img);
    cudaGetSymbolAddress((void**)&p_hproj, g_hproj);
    cudaGetSymbolAddress((void**)&p_gate,  g_gate);
    cudaGetSymbolAddress((void**)&p_xc,    g_xc);
    cudaGetSymbolAddress((void**)&p_emb,   g_emb);
    cudaGetSymbolAddress((void**)&p_embW,  g_embW);
    cudaGetSymbolAddress((void**)&p_hall,  g_hall);
    cudaGetSymbolAddress((void**)&p_pph,   g_pp_h);
    cudaGetSymbolAddress((void**)&p_ppg,   g_pp_g);
    cudaGetSymbolAddress((void**)&p_pa,    g_pa);
    cudaGetSymbolAddress((void**)&p_pb,    g_pb);
    cudaGetSymbolAddress((void**)&p_pih,   g_pi_h);
    cudaGetSymbolAddress((void**)&p_pic,   g_pi_c);

    // ---- setup ----
    avg_kernel<<<64, 256>>>(img);
    // init h0/c0: avg @ W_init_{h,c}  (K=2048, ks=8)
    gemm_pass<<<256, 64>>>(p_avg, Dn, W_init_h, Hn, p_pih, Hn, Dn, 8, 16,
                           p_avg, Dn, W_init_c, Hn, p_pic, Hn, Dn, 8, 16);
    reduce2_kernel<<<128, 256>>>(p_h, p_pih, 8, Hn, b_init_h, 1, Bsz * Hn,
                                 p_c, p_pic, 8, Hn, b_init_c, 1, Bsz * Hn);
    // att_img = img @ W_att_img + b : M=6272, N=512, K=2048
    gemm_big<0><<<dim3(Hn / 64, (Bsz * Pn) / 64), 128>>>(img, Dn, W_att_im, Hn, b_att_im,
                                                         p_att, Hn, Bsz * Pn, Hn, Dn);
    emb_kernel<<<(Bsz * Tn * Hn) / 256, 256>>>(caps, E);
    // embW = emb_all @ Wih_top : M=608, N=2048, K=512
    gemm_big<0><<<dim3(4 * Hn / 64, 10), 128>>>(p_emb, Hn, Wih, 4 * Hn, nullptr,
                                                p_embW, 4 * Hn, Bsz * Tn, 4 * Hn, Hn);

    // ---- recurrent steps ----
    for (int t = 0; t < Tn; t++) {
        // pass1: hproj = h@W_att_h (N=512,K=512,ks=2) ; gatep = h@W_fbeta (N=2048,K=512,ks=2)
        gemm_pass<<<32 + 128, 64>>>(p_h, Hn, W_att_h, Hn, p_pph, Hn, Hn, 2, 16,
                                    p_h, Hn, W_fbeta, Dn, p_ppg, Dn, Hn, 2, 64);
        reduce2_kernel<<<(Bsz * Hn + Bsz * Dn) / 256, 256>>>(
            p_hproj, p_pph, 2, Hn, b_att_h, 0, Bsz * Hn,
            p_gate,  p_ppg, 2, Dn, b_fbeta, 2, Bsz * Dn);
        scores_kernel<<<(Bsz * Pn) / 8, 256>>>(v_att, b_v_att);
        softmax_kernel<<<Bsz, 256>>>(alphas, t);
        context_kernel<<<Bsz * 16, 128>>>(img);
        // pass2: pa = xc@Wih_bot (N=2048,K=2048,ks=4) ; pb = h@Whh (N=2048,K=512,ks=1)
        gemm_pass<<<256 + 64, 64>>>(p_xc, Dn, Wih + (size_t)Hn * 4 * Hn, 4 * Hn, p_pa, 4 * Hn, Dn, 4, 64,
                                    p_h,  Hn, Whh,                        4 * Hn, p_pb, 4 * Hn, Hn, 1, 64);
        lstm_kernel<<<(Bsz * Hn) / 256, 256>>>(bih, bhh, t);
    }

    // ---- final: preds = h_all @ W_out + b_out : M=608, N=30000, K=512 ----
    gemm_big<1><<<dim3((Vn + 63) / 64, 10), 128>>>(p_hall, Hn, W_out, Vn, b_out,
                                                   preds, Vn, Tn * Bsz, Vn, Hn);
}